// round 4
// baseline (speedup 1.0000x reference)
#include <cuda_runtime.h>
#include <math.h>

#define N_NODES  200000
#define N_HEDGES 100000
#define N_INC    1600000
#define D        64

// ---------------- scratch (static device globals; no allocation) ------------
__device__ float g_hedge_proj[N_HEDGES * D];   // hedge_features @ W_nh
__device__ float g_node_proj [N_NODES  * D];   // new_node @ W_hn
__device__ float g_gate_node [N_NODES  * D];   // segment_sum -> nodes
__device__ float g_gate_hedge[N_HEDGES * D];   // segment_sum -> hedges

// ---------------- zero the two gate accumulators ----------------------------
__global__ void zero_gates_kernel() {
    const int n_node4  = N_NODES  * D / 4;
    const int n_hedge4 = N_HEDGES * D / 4;
    int i = blockIdx.x * blockDim.x + threadIdx.x;
    float4 z = make_float4(0.f, 0.f, 0.f, 0.f);
    if (i < n_node4) {
        ((float4*)g_gate_node)[i] = z;
    } else if (i < n_node4 + n_hedge4) {
        ((float4*)g_gate_hedge)[i - n_node4] = z;
    }
}

// ---------------- fused GEMM (+ optional gate*tanh epilogue) ----------------
// out[r][c] = sum_k X[r][k] * W[k][c]          (MODE==0)
// out[r][c] = tanhf( (X@W)[r][c] * gate[r][c] )(MODE==1)
// 128 threads/block, 64 rows/block, TM=4 x TN=8 register tile.
template <int MODE>
__global__ __launch_bounds__(128)
void proj_kernel(const float* __restrict__ X, const float* __restrict__ W,
                 const float* __restrict__ gate, float* __restrict__ out, int M)
{
    __shared__ float Ws[64 * 64];       // W row-major copy
    __shared__ float Xs[64 * 65];       // Xs[r][k], k-stride padded to 65

    const int t    = threadIdx.x;
    const int rg   = t >> 3;            // 0..15  (row group: 4 rows)
    const int cg   = t & 7;             // 0..7   (col group: 8 cols)
    const int row0 = blockIdx.x * 64;

    // stage W (4096 floats, 8 float4 per thread)
    const float4* W4 = (const float4*)W;
    float4* Ws4 = (float4*)Ws;
    #pragma unroll
    for (int jj = 0; jj < 8; jj++) {
        int i4 = t + jj * 128;
        Ws4[i4] = W4[i4];
    }

    // stage X tile (64 rows x 64 k), transposed-stride layout Xs[r*65 + k]
    const float4* X4 = (const float4*)X;
    #pragma unroll
    for (int jj = 0; jj < 8; jj++) {
        int i4  = t + jj * 128;
        int r   = i4 >> 4;              // 0..63
        int kq  = i4 & 15;              // float4 index within row
        int row = row0 + r;
        float4 v = make_float4(0.f, 0.f, 0.f, 0.f);
        if (row < M) v = X4[row * 16 + kq];
        float* xp = &Xs[r * 65 + kq * 4];
        xp[0] = v.x; xp[1] = v.y; xp[2] = v.z; xp[3] = v.w;
    }
    __syncthreads();

    float acc[4][8];
    #pragma unroll
    for (int i = 0; i < 4; i++)
        #pragma unroll
        for (int j = 0; j < 8; j++) acc[i][j] = 0.f;

    #pragma unroll 8
    for (int k = 0; k < 64; k++) {
        float4 w0 = *(const float4*)&Ws[k * 64 + cg * 8];
        float4 w1 = *(const float4*)&Ws[k * 64 + cg * 8 + 4];
        float xv[4];
        #pragma unroll
        for (int i = 0; i < 4; i++) xv[i] = Xs[(rg * 4 + i) * 65 + k];
        #pragma unroll
        for (int i = 0; i < 4; i++) {
            acc[i][0] = fmaf(xv[i], w0.x, acc[i][0]);
            acc[i][1] = fmaf(xv[i], w0.y, acc[i][1]);
            acc[i][2] = fmaf(xv[i], w0.z, acc[i][2]);
            acc[i][3] = fmaf(xv[i], w0.w, acc[i][3]);
            acc[i][4] = fmaf(xv[i], w1.x, acc[i][4]);
            acc[i][5] = fmaf(xv[i], w1.y, acc[i][5]);
            acc[i][6] = fmaf(xv[i], w1.z, acc[i][6]);
            acc[i][7] = fmaf(xv[i], w1.w, acc[i][7]);
        }
    }

    // epilogue
    #pragma unroll
    for (int i = 0; i < 4; i++) {
        int row = row0 + rg * 4 + i;
        if (row < M) {
            int off = row * 64 + cg * 8;
            float4 o0, o1;
            if (MODE == 1) {
                float4 gz0 = *(const float4*)&gate[off];
                float4 gz1 = *(const float4*)&gate[off + 4];
                o0.x = tanhf(acc[i][0] * gz0.x);
                o0.y = tanhf(acc[i][1] * gz0.y);
                o0.z = tanhf(acc[i][2] * gz0.z);
                o0.w = tanhf(acc[i][3] * gz0.w);
                o1.x = tanhf(acc[i][4] * gz1.x);
                o1.y = tanhf(acc[i][5] * gz1.y);
                o1.z = tanhf(acc[i][6] * gz1.z);
                o1.w = tanhf(acc[i][7] * gz1.w);
            } else {
                o0 = make_float4(acc[i][0], acc[i][1], acc[i][2], acc[i][3]);
                o1 = make_float4(acc[i][4], acc[i][5], acc[i][6], acc[i][7]);
            }
            *(float4*)&out[off]     = o0;
            *(float4*)&out[off + 4] = o1;
        }
    }
}

// ---------------- segment-sum scatter ---------------------------------------
// dst[sidx[i]] += src[gidx[i]]  (rows of 64 f32). 16 lanes per incidence,
// one float4 per lane, vectorized reduction (sm_90+ red.global.add.v4.f32).
__global__ __launch_bounds__(256)
void scatter_kernel(const float* __restrict__ src,
                    const int* __restrict__ gidx,
                    const int* __restrict__ sidx,
                    float* __restrict__ dst)
{
    int inc = blockIdx.x * 16 + (threadIdx.x >> 4);
    int j   = threadIdx.x & 15;
    int g = __ldg(&gidx[inc]);
    int s = __ldg(&sidx[inc]);
    float4 v = ((const float4*)src)[g * 16 + j];
    float* p = dst + (size_t)s * 64 + j * 4;
    asm volatile("red.global.add.v4.f32 [%0], {%1,%2,%3,%4};"
                 :: "l"(p), "f"(v.x), "f"(v.y), "f"(v.z), "f"(v.w)
                 : "memory");
}

// ---------------- launch ----------------------------------------------------
extern "C" void kernel_launch(void* const* d_in, const int* in_sizes, int n_in,
                              void* d_out, int out_size)
{
    const float* node_f   = (const float*)d_in[0];
    const float* hedge_f  = (const float*)d_in[1];
    const float* W_nn     = (const float*)d_in[2];
    const float* W_nh     = (const float*)d_in[3];
    const float* W_hh     = (const float*)d_in[4];
    const float* W_hn     = (const float*)d_in[5];
    const int*   node_idx = (const int*)d_in[6];
    const int*   hedge_idx= (const int*)d_in[7];

    float* out_node  = (float*)d_out;                       // [N_NODES, 64]
    float* out_hedge = out_node + (size_t)N_NODES * D;      // [N_HEDGES, 64]

    float *hp, *np, *gn, *gh;
    cudaGetSymbolAddress((void**)&hp, g_hedge_proj);
    cudaGetSymbolAddress((void**)&np, g_node_proj);
    cudaGetSymbolAddress((void**)&gn, g_gate_node);
    cudaGetSymbolAddress((void**)&gh, g_gate_hedge);

    const int n_gate4   = (N_NODES + N_HEDGES) * D / 4;
    const int zero_grid = (n_gate4 + 255) / 256;
    const int grid_n    = (N_NODES  + 63) / 64;   // 3125
    const int grid_h    = (N_HEDGES + 63) / 64;   // 1563
    const int grid_sc   = N_INC / 16;             // 100000

    // 1) zero gate accumulators
    zero_gates_kernel<<<zero_grid, 256>>>();
    // 2) hedge_proj = hedge_features @ W_nh
    proj_kernel<0><<<grid_h, 128>>>(hedge_f, W_nh, nullptr, hp, N_HEDGES);
    // 3) gate_node = segment_sum(hedge_proj[hedge_idx], node_idx)
    scatter_kernel<<<grid_sc, 256>>>(hp, hedge_idx, node_idx, gn);
    // 4) new_node = tanh((node_features @ W_nn) * gate_node)
    proj_kernel<1><<<grid_n, 128>>>(node_f, W_nn, gn, out_node, N_NODES);
    // 5) node_proj = new_node @ W_hn
    proj_kernel<0><<<grid_n, 128>>>(out_node, W_hn, nullptr, np, N_NODES);
    // 6) gate_hedge = segment_sum(node_proj[node_idx], hedge_idx)
    scatter_kernel<<<grid_sc, 256>>>(np, node_idx, hedge_idx, gh);
    // 7) new_hedge = tanh((hedge_features @ W_hh) * gate_hedge)
    proj_kernel<1><<<grid_h, 128>>>(hedge_f, W_hh, gh, out_hedge, N_HEDGES);
}

// round 11
// speedup vs baseline: 1.0635x; 1.0635x over previous
#include <cuda_runtime.h>
#include <math.h>

#define N_NODES  200000
#define N_HEDGES 100000
#define N_INC    1600000
#define D        64

// ---------------- scratch (static device globals; no allocation) ------------
__device__ float g_hedge_proj[N_HEDGES * D];   // hedge_features @ W_nh
__device__ float g_node_proj [N_NODES  * D];   // new_node @ W_hn
__device__ float g_gate_node [N_NODES  * D];   // segment_sum -> nodes
__device__ float g_gate_hedge[N_HEDGES * D];   // segment_sum -> hedges

// ---------------- helpers ----------------------------------------------------
// tf32 "hi" part as raw b32 (valid fp32 with low mantissa bits zeroed)
__device__ __forceinline__ unsigned tf_hi(float f) {
    unsigned r;
    asm("cvt.rna.tf32.f32 %0, %1;" : "=r"(r) : "f"(f));
    return r;
}

__device__ __forceinline__ void mma_tf32(float* c,
                                         unsigned a0, unsigned a1, unsigned a2, unsigned a3,
                                         unsigned b0, unsigned b1)
{
    asm volatile(
        "mma.sync.aligned.m16n8k8.row.col.f32.tf32.tf32.f32 "
        "{%0,%1,%2,%3}, {%4,%5,%6,%7}, {%8,%9}, {%0,%1,%2,%3};"
        : "+f"(c[0]), "+f"(c[1]), "+f"(c[2]), "+f"(c[3])
        : "r"(a0), "r"(a1), "r"(a2), "r"(a3), "r"(b0), "r"(b1));
}

// ---------------- 3xTF32 tensor-core GEMM (+ optional gate*tanh epilogue) ----
// out[r][c] = X[r][:] @ W[:][c]               (MODE==0)
// out[r][c] = tanhf((X@W)[r][c] * gate[r][c]) (MODE==1)
// 128 threads (4 warps), 64 rows/block; warp w computes rows [w*16, w*16+16).
// W is split hi/lo ONCE at staging (Ws_hi/Ws_lo); A is split in registers.
// acc += ah*bh + al*bh + ah*bl  (3xTF32, per-product error ~2^-21).
// Smem stride 68: A-frag bank = (4*grp+tig)%32, B-frag bank = (4*tig+grp+8nt)%32
// -> both conflict-free permutations.
template <int MODE>
__global__ __launch_bounds__(128)
void proj_mma_kernel(const float* __restrict__ X, const float* __restrict__ W,
                     const float* __restrict__ gate, float* __restrict__ out, int M)
{
    __shared__ float Xs   [64 * 68];   // [row][k], raw fp32
    __shared__ float Ws_hi[64 * 68];   // [k][n], tf32 hi part
    __shared__ float Ws_lo[64 * 68];   // [k][n], tf32 lo part

    const int t    = threadIdx.x;
    const int row0 = blockIdx.x * 64;

    // stage W (64x64) with hi/lo split
    {
        const float4* W4 = (const float4*)W;
        #pragma unroll
        for (int jj = 0; jj < 8; jj++) {
            int i4 = t + jj * 128;          // 0..1023
            int k  = i4 >> 4;
            int n4 = i4 & 15;
            float4 v = W4[i4];
            float* ph = &Ws_hi[k * 68 + n4 * 4];
            float* pl = &Ws_lo[k * 68 + n4 * 4];
            float h;
            h = __uint_as_float(tf_hi(v.x)); ph[0] = h; pl[0] = __uint_as_float(tf_hi(v.x - h));
            h = __uint_as_float(tf_hi(v.y)); ph[1] = h; pl[1] = __uint_as_float(tf_hi(v.y - h));
            h = __uint_as_float(tf_hi(v.z)); ph[2] = h; pl[2] = __uint_as_float(tf_hi(v.z - h));
            h = __uint_as_float(tf_hi(v.w)); ph[3] = h; pl[3] = __uint_as_float(tf_hi(v.w - h));
        }
    }
    // stage X tile (64 rows), raw fp32 (A split done in registers)
    {
        const float4* X4 = (const float4*)X;
        #pragma unroll
        for (int jj = 0; jj < 8; jj++) {
            int i4  = t + jj * 128;
            int r   = i4 >> 4;
            int kq  = i4 & 15;
            int row = row0 + r;
            float4 v = make_float4(0.f, 0.f, 0.f, 0.f);
            if (row < M) v = X4[row * 16 + kq];
            float* p = &Xs[r * 68 + kq * 4];
            p[0] = v.x; p[1] = v.y; p[2] = v.z; p[3] = v.w;
        }
    }
    __syncthreads();

    const int lane = t & 31;
    const int w    = t >> 5;        // warp id: rows w*16..w*16+15
    const int grp  = lane >> 2;     // 0..7
    const int tig  = lane & 3;      // 0..3

    float acc[8][4];
    #pragma unroll
    for (int nt = 0; nt < 8; nt++)
        #pragma unroll
        for (int j = 0; j < 4; j++) acc[nt][j] = 0.f;

    const float* xr0 = &Xs[(w * 16 + grp) * 68];
    const float* xr1 = &Xs[(w * 16 + grp + 8) * 68];

    #pragma unroll
    for (int kk = 0; kk < 8; kk++) {
        const int kb = kk * 8;
        // A fragment: hi/lo split in registers (8 cvt + 4 sub per k-step)
        float xv[4];
        xv[0] = xr0[kb + tig];
        xv[1] = xr1[kb + tig];
        xv[2] = xr0[kb + tig + 4];
        xv[3] = xr1[kb + tig + 4];
        unsigned ah[4], al[4];
        #pragma unroll
        for (int i = 0; i < 4; i++) {
            ah[i] = tf_hi(xv[i]);
            al[i] = tf_hi(xv[i] - __uint_as_float(ah[i]));
        }
        const int b0off = (kb + tig) * 68 + grp;
        const int b1off = (kb + tig + 4) * 68 + grp;
        #pragma unroll
        for (int nt = 0; nt < 8; nt++) {
            unsigned bh0 = __float_as_uint(Ws_hi[b0off + nt * 8]);
            unsigned bh1 = __float_as_uint(Ws_hi[b1off + nt * 8]);
            unsigned bl0 = __float_as_uint(Ws_lo[b0off + nt * 8]);
            unsigned bl1 = __float_as_uint(Ws_lo[b1off + nt * 8]);
            mma_tf32(acc[nt], ah[0], ah[1], ah[2], ah[3], bh0, bh1);
            mma_tf32(acc[nt], al[0], al[1], al[2], al[3], bh0, bh1);
            mma_tf32(acc[nt], ah[0], ah[1], ah[2], ah[3], bl0, bl1);
        }
    }

    // epilogue: c0/c1 -> (row r0, cols 2*tig, 2*tig+1), c2/c3 -> row r0+8
    const int r0 = row0 + w * 16 + grp;
    const int r1 = r0 + 8;
    #pragma unroll
    for (int nt = 0; nt < 8; nt++) {
        const int c = nt * 8 + tig * 2;
        if (r0 < M) {
            float2 o;
            if (MODE == 1) {
                float2 g = *(const float2*)&gate[r0 * 64 + c];
                o.x = tanhf(acc[nt][0] * g.x);
                o.y = tanhf(acc[nt][1] * g.y);
            } else {
                o.x = acc[nt][0]; o.y = acc[nt][1];
            }
            *(float2*)&out[r0 * 64 + c] = o;
        }
        if (r1 < M) {
            float2 o;
            if (MODE == 1) {
                float2 g = *(const float2*)&gate[r1 * 64 + c];
                o.x = tanhf(acc[nt][2] * g.x);
                o.y = tanhf(acc[nt][3] * g.y);
            } else {
                o.x = acc[nt][2]; o.y = acc[nt][3];
            }
            *(float2*)&out[r1 * 64 + c] = o;
        }
    }
}

// ---------------- segment-sum scatter ---------------------------------------
// dst[sidx[i]] += src[gidx[i]]  (rows of 64 f32). 16 lanes per incidence,
// one float4 per lane, vectorized reduction (red.global.add.v4.f32).
__global__ __launch_bounds__(256)
void scatter_kernel(const float* __restrict__ src,
                    const int* __restrict__ gidx,
                    const int* __restrict__ sidx,
                    float* __restrict__ dst)
{
    int inc = blockIdx.x * 16 + (threadIdx.x >> 4);
    int j   = threadIdx.x & 15;
    int g = __ldg(&gidx[inc]);
    int s = __ldg(&sidx[inc]);
    float4 v = ((const float4*)src)[g * 16 + j];
    float* p = dst + (size_t)s * 64 + j * 4;
    asm volatile("red.global.add.v4.f32 [%0], {%1,%2,%3,%4};"
                 :: "l"(p), "f"(v.x), "f"(v.y), "f"(v.z), "f"(v.w)
                 : "memory");
}

// ---------------- launch ----------------------------------------------------
extern "C" void kernel_launch(void* const* d_in, const int* in_sizes, int n_in,
                              void* d_out, int out_size)
{
    const float* node_f    = (const float*)d_in[0];
    const float* hedge_f   = (const float*)d_in[1];
    const float* W_nn      = (const float*)d_in[2];
    const float* W_nh      = (const float*)d_in[3];
    const float* W_hh      = (const float*)d_in[4];
    const float* W_hn      = (const float*)d_in[5];
    const int*   node_idx  = (const int*)d_in[6];
    const int*   hedge_idx = (const int*)d_in[7];

    float* out_node  = (float*)d_out;                       // [N_NODES, 64]
    float* out_hedge = out_node + (size_t)N_NODES * D;      // [N_HEDGES, 64]

    float *hp, *np, *gn, *gh;
    cudaGetSymbolAddress((void**)&hp, g_hedge_proj);
    cudaGetSymbolAddress((void**)&np, g_node_proj);
    cudaGetSymbolAddress((void**)&gn, g_gate_node);
    cudaGetSymbolAddress((void**)&gh, g_gate_hedge);

    const int grid_n  = (N_NODES  + 63) / 64;   // 3125
    const int grid_h  = (N_HEDGES + 63) / 64;   // 1563
    const int grid_sc = N_INC / 16;             // 100000

    // 1) zero gate accumulators (memset engine nodes in the graph)
    cudaMemsetAsync(gn, 0, (size_t)N_NODES  * D * sizeof(float), 0);
    cudaMemsetAsync(gh, 0, (size_t)N_HEDGES * D * sizeof(float), 0);
    // 2) hedge_proj = hedge_features @ W_nh
    proj_mma_kernel<0><<<grid_h, 128>>>(hedge_f, W_nh, nullptr, hp, N_HEDGES);
    // 3) gate_node = segment_sum(hedge_proj[hedge_idx], node_idx)
    scatter_kernel<<<grid_sc, 256>>>(hp, hedge_idx, node_idx, gn);
    // 4) new_node = tanh((node_features @ W_nn) * gate_node)
    proj_mma_kernel<1><<<grid_n, 128>>>(node_f, W_nn, gn, out_node, N_NODES);
    // 5) node_proj = new_node @ W_hn
    proj_mma_kernel<0><<<grid_n, 128>>>(out_node, W_hn, nullptr, np, N_NODES);
    // 6) gate_hedge = segment_sum(node_proj[node_idx], hedge_idx)
    scatter_kernel<<<grid_sc, 256>>>(np, node_idx, hedge_idx, gh);
    // 7) new_hedge = tanh((hedge_features @ W_hh) * gate_hedge)
    proj_mma_kernel<1><<<grid_h, 128>>>(hedge_f, W_hh, gh, out_hedge, N_HEDGES);
}

// round 12
// speedup vs baseline: 1.1972x; 1.1257x over previous
#include <cuda_runtime.h>
#include <math.h>

#define N_NODES  200000
#define N_HEDGES 100000
#define N_INC    1600000
#define D        64

// ---------------- scratch (static device globals; no allocation) ------------
__device__ float g_hedge_proj[N_HEDGES * D];   // hedge_features @ W_nh
__device__ float g_node_proj [N_NODES  * D];   // new_node @ W_hn
__device__ float g_gate_node [N_NODES  * D];   // segment_sum -> nodes
__device__ float g_gate_hedge[N_HEDGES * D];   // segment_sum -> hedges

// ---------------- helpers ----------------------------------------------------
// tf32 "hi" part as raw b32 (valid fp32 with low mantissa bits zeroed)
__device__ __forceinline__ unsigned tf_hi(float f) {
    unsigned r;
    asm("cvt.rna.tf32.f32 %0, %1;" : "=r"(r) : "f"(f));
    return r;
}

__device__ __forceinline__ void mma_tf32(float* c,
                                         unsigned a0, unsigned a1, unsigned a2, unsigned a3,
                                         unsigned b0, unsigned b1)
{
    asm volatile(
        "mma.sync.aligned.m16n8k8.row.col.f32.tf32.tf32.f32 "
        "{%0,%1,%2,%3}, {%4,%5,%6,%7}, {%8,%9}, {%0,%1,%2,%3};"
        : "+f"(c[0]), "+f"(c[1]), "+f"(c[2]), "+f"(c[3])
        : "r"(a0), "r"(a1), "r"(a2), "r"(a3), "r"(b0), "r"(b1));
}

// ---------------- 3xTF32 tensor-core GEMM (+ optional gate*tanh epilogue) ----
// out[r][c] = X[r][:] @ W[:][c]               (MODE==0)
// out[r][c] = tanhf((X@W)[r][c] * gate[r][c]) (MODE==1)
// 256 threads (8 warps), 128 rows/block. Warp grid 4(m) x 2(n): warp tile 32x32.
// B (=W hi/lo) is pre-packed into smem in MMA fragment order as float4
// {bh0,bh1,bl0,bl1}[nt][kk][lane] -> one LDS.128 per (nt,kk) in the mainloop.
// A stays in stride-68 row-major smem (conflict-free scalar LDS), hi/lo split
// in registers. acc += ah*bh + al*bh + ah*bl (3xTF32, error ~2^-21).
template <int MODE>
__global__ __launch_bounds__(256)
void proj_mma_kernel(const float* __restrict__ X, const float* __restrict__ W,
                     const float* __restrict__ gate, float* __restrict__ out, int M)
{
    __shared__ float  Xs[128 * 68];            // [row][k], raw fp32 (34.8 KB)
    __shared__ float4 Bfrag[8 * 8 * 32];       // [nt][kk][lane]        (32 KB)

    const int t    = threadIdx.x;
    const int row0 = blockIdx.x * 128;

    // ---- build B fragments straight from global W (16 KB, L2-hot) ----------
    // warp w handles kk=w; lanes map to (grp,tig); nt loops 0..7.
    {
        const int lane = t & 31;
        const int kk   = t >> 5;               // 0..7
        const int grp  = lane >> 2;
        const int tig  = lane & 3;
        const int base = (kk * 8 + tig) * 64 + grp;   // W[k=kk*8+tig][n=grp]
        #pragma unroll
        for (int nt = 0; nt < 8; nt++) {
            float v0 = __ldg(&W[base + nt * 8]);            // k = kk*8+tig
            float v1 = __ldg(&W[base + 4 * 64 + nt * 8]);   // k = kk*8+tig+4
            float h0 = __uint_as_float(tf_hi(v0));
            float h1 = __uint_as_float(tf_hi(v1));
            float l0 = __uint_as_float(tf_hi(v0 - h0));
            float l1 = __uint_as_float(tf_hi(v1 - h1));
            Bfrag[(nt * 8 + kk) * 32 + lane] = make_float4(h0, h1, l0, l1);
        }
    }
    // ---- stage X tile (128 rows), raw fp32 ---------------------------------
    {
        const float4* X4 = (const float4*)X;
        #pragma unroll
        for (int jj = 0; jj < 8; jj++) {
            int i4  = t + jj * 256;            // 0..2047
            int r   = i4 >> 4;                 // 0..127
            int kq  = i4 & 15;
            int row = row0 + r;
            float4 v = make_float4(0.f, 0.f, 0.f, 0.f);
            if (row < M) v = X4[row * 16 + kq];
            float* p = &Xs[r * 68 + kq * 4];
            p[0] = v.x; p[1] = v.y; p[2] = v.z; p[3] = v.w;
        }
    }
    __syncthreads();

    const int lane = t & 31;
    const int w    = t >> 5;
    const int mw   = w >> 1;        // 0..3 : rows [mw*32, mw*32+32)
    const int nw   = w & 1;         // 0..1 : cols [nw*32, nw*32+32)
    const int grp  = lane >> 2;     // 0..7
    const int tig  = lane & 3;      // 0..3

    float acc[2][4][4];
    #pragma unroll
    for (int mt = 0; mt < 2; mt++)
        #pragma unroll
        for (int nt = 0; nt < 4; nt++)
            #pragma unroll
            for (int j = 0; j < 4; j++) acc[mt][nt][j] = 0.f;

    // A row pointers: [mt][half]
    const float* xr00 = &Xs[(mw * 32 +      grp) * 68];
    const float* xr01 = &Xs[(mw * 32 +  8 + grp) * 68];
    const float* xr10 = &Xs[(mw * 32 + 16 + grp) * 68];
    const float* xr11 = &Xs[(mw * 32 + 24 + grp) * 68];

    #pragma unroll
    for (int kk = 0; kk < 8; kk++) {
        const int kb = kk * 8;
        // A fragments for both m-tiles: hi/lo split in registers
        unsigned ah[2][4], al[2][4];
        {
            float x0, x1, x2, x3;
            x0 = xr00[kb + tig]; x1 = xr01[kb + tig];
            x2 = xr00[kb + tig + 4]; x3 = xr01[kb + tig + 4];
            ah[0][0] = tf_hi(x0); al[0][0] = tf_hi(x0 - __uint_as_float(ah[0][0]));
            ah[0][1] = tf_hi(x1); al[0][1] = tf_hi(x1 - __uint_as_float(ah[0][1]));
            ah[0][2] = tf_hi(x2); al[0][2] = tf_hi(x2 - __uint_as_float(ah[0][2]));
            ah[0][3] = tf_hi(x3); al[0][3] = tf_hi(x3 - __uint_as_float(ah[0][3]));
            x0 = xr10[kb + tig]; x1 = xr11[kb + tig];
            x2 = xr10[kb + tig + 4]; x3 = xr11[kb + tig + 4];
            ah[1][0] = tf_hi(x0); al[1][0] = tf_hi(x0 - __uint_as_float(ah[1][0]));
            ah[1][1] = tf_hi(x1); al[1][1] = tf_hi(x1 - __uint_as_float(ah[1][1]));
            ah[1][2] = tf_hi(x2); al[1][2] = tf_hi(x2 - __uint_as_float(ah[1][2]));
            ah[1][3] = tf_hi(x3); al[1][3] = tf_hi(x3 - __uint_as_float(ah[1][3]));
        }
        #pragma unroll
        for (int nt = 0; nt < 4; nt++) {
            float4 b = Bfrag[((nw * 4 + nt) * 8 + kk) * 32 + lane];
            unsigned bh0 = __float_as_uint(b.x);
            unsigned bh1 = __float_as_uint(b.y);
            unsigned bl0 = __float_as_uint(b.z);
            unsigned bl1 = __float_as_uint(b.w);
            #pragma unroll
            for (int mt = 0; mt < 2; mt++) {
                mma_tf32(acc[mt][nt], ah[mt][0], ah[mt][1], ah[mt][2], ah[mt][3], bh0, bh1);
                mma_tf32(acc[mt][nt], al[mt][0], al[mt][1], al[mt][2], al[mt][3], bh0, bh1);
                mma_tf32(acc[mt][nt], ah[mt][0], ah[mt][1], ah[mt][2], ah[mt][3], bl0, bl1);
            }
        }
    }

    // ---- epilogue ----------------------------------------------------------
    #pragma unroll
    for (int mt = 0; mt < 2; mt++) {
        const int r0 = row0 + mw * 32 + mt * 16 + grp;
        const int r1 = r0 + 8;
        #pragma unroll
        for (int nt = 0; nt < 4; nt++) {
            const int c = nw * 32 + nt * 8 + tig * 2;
            if (r0 < M) {
                float2 o;
                if (MODE == 1) {
                    float2 g = *(const float2*)&gate[r0 * 64 + c];
                    o.x = tanhf(acc[mt][nt][0] * g.x);
                    o.y = tanhf(acc[mt][nt][1] * g.y);
                } else {
                    o.x = acc[mt][nt][0]; o.y = acc[mt][nt][1];
                }
                *(float2*)&out[r0 * 64 + c] = o;
            }
            if (r1 < M) {
                float2 o;
                if (MODE == 1) {
                    float2 g = *(const float2*)&gate[r1 * 64 + c];
                    o.x = tanhf(acc[mt][nt][2] * g.x);
                    o.y = tanhf(acc[mt][nt][3] * g.y);
                } else {
                    o.x = acc[mt][nt][2]; o.y = acc[mt][nt][3];
                }
                *(float2*)&out[r1 * 64 + c] = o;
            }
        }
    }
}

// ---------------- segment-sum scatter ---------------------------------------
// dst[sidx[i]] += src[gidx[i]]  (rows of 64 f32). 16 lanes per incidence,
// one float4 per lane, vectorized reduction (red.global.add.v4.f32).
__global__ __launch_bounds__(256)
void scatter_kernel(const float* __restrict__ src,
                    const int* __restrict__ gidx,
                    const int* __restrict__ sidx,
                    float* __restrict__ dst)
{
    int inc = blockIdx.x * 16 + (threadIdx.x >> 4);
    int j   = threadIdx.x & 15;
    int g = __ldg(&gidx[inc]);
    int s = __ldg(&sidx[inc]);
    float4 v = ((const float4*)src)[g * 16 + j];
    float* p = dst + (size_t)s * 64 + j * 4;
    asm volatile("red.global.add.v4.f32 [%0], {%1,%2,%3,%4};"
                 :: "l"(p), "f"(v.x), "f"(v.y), "f"(v.z), "f"(v.w)
                 : "memory");
}

// ---------------- launch ----------------------------------------------------
extern "C" void kernel_launch(void* const* d_in, const int* in_sizes, int n_in,
                              void* d_out, int out_size)
{
    const float* node_f    = (const float*)d_in[0];
    const float* hedge_f   = (const float*)d_in[1];
    const float* W_nn      = (const float*)d_in[2];
    const float* W_nh      = (const float*)d_in[3];
    const float* W_hh      = (const float*)d_in[4];
    const float* W_hn      = (const float*)d_in[5];
    const int*   node_idx  = (const int*)d_in[6];
    const int*   hedge_idx = (const int*)d_in[7];

    float* out_node  = (float*)d_out;                       // [N_NODES, 64]
    float* out_hedge = out_node + (size_t)N_NODES * D;      // [N_HEDGES, 64]

    float *hp, *np, *gn, *gh;
    cudaGetSymbolAddress((void**)&hp, g_hedge_proj);
    cudaGetSymbolAddress((void**)&np, g_node_proj);
    cudaGetSymbolAddress((void**)&gn, g_gate_node);
    cudaGetSymbolAddress((void**)&gh, g_gate_hedge);

    const int grid_n  = (N_NODES  + 127) / 128;   // 1563
    const int grid_h  = (N_HEDGES + 127) / 128;   // 782
    const int grid_sc = N_INC / 16;               // 100000

    // 1) zero gate accumulators (memset engine nodes in the graph)
    cudaMemsetAsync(gn, 0, (size_t)N_NODES  * D * sizeof(float), 0);
    cudaMemsetAsync(gh, 0, (size_t)N_HEDGES * D * sizeof(float), 0);
    // 2) hedge_proj = hedge_features @ W_nh
    proj_mma_kernel<0><<<grid_h, 256>>>(hedge_f, W_nh, nullptr, hp, N_HEDGES);
    // 3) gate_node = segment_sum(hedge_proj[hedge_idx], node_idx)
    scatter_kernel<<<grid_sc, 256>>>(hp, hedge_idx, node_idx, gn);
    // 4) new_node = tanh((node_features @ W_nn) * gate_node)
    proj_mma_kernel<1><<<grid_n, 256>>>(node_f, W_nn, gn, out_node, N_NODES);
    // 5) node_proj = new_node @ W_hn
    proj_mma_kernel<0><<<grid_n, 256>>>(out_node, W_hn, nullptr, np, N_NODES);
    // 6) gate_hedge = segment_sum(node_proj[node_idx], hedge_idx)
    scatter_kernel<<<grid_sc, 256>>>(np, node_idx, hedge_idx, gh);
    // 7) new_hedge = tanh((hedge_features @ W_hh) * gate_hedge)
    proj_mma_kernel<1><<<grid_h, 256>>>(hedge_f, W_hh, gh, out_hedge, N_HEDGES);
}

// round 13
// speedup vs baseline: 1.4875x; 1.2425x over previous
#include <cuda_runtime.h>
#include <math.h>

#define N_NODES  200000
#define N_HEDGES 100000
#define N_INC    1600000
#define D        64
#define N_SEG    (N_NODES + N_HEDGES)       // 300000
#define SCAN_BLOCKS 74                       // ceil(300000 / 4096)

// ---------------- scratch (static device globals; no allocation) ------------
__device__ float g_hedge_proj[N_HEDGES * D];   // hedge_features @ W_nh
__device__ float g_node_proj [N_NODES  * D];   // new_node @ W_hn
__device__ float g_gate_node [N_NODES  * D];   // segment_sum -> nodes
__device__ float g_gate_hedge[N_HEDGES * D];   // segment_sum -> hedges
__device__ int   g_hist[N_SEG];                // counts, then reused as cursors
__device__ int   g_off [N_SEG + 1];            // CSR offsets (combined node|hedge)
__device__ int   g_blocksums[128];
__device__ int   g_ord[2 * N_INC];             // CSR adjacency (source row ids)

// ---------------- helpers ----------------------------------------------------
__device__ __forceinline__ unsigned tf_hi(float f) {
    unsigned r;
    asm("cvt.rna.tf32.f32 %0, %1;" : "=r"(r) : "f"(f));
    return r;
}

__device__ __forceinline__ void mma_tf32(float* c,
                                         unsigned a0, unsigned a1, unsigned a2, unsigned a3,
                                         unsigned b0, unsigned b1)
{
    asm volatile(
        "mma.sync.aligned.m16n8k8.row.col.f32.tf32.tf32.f32 "
        "{%0,%1,%2,%3}, {%4,%5,%6,%7}, {%8,%9}, {%0,%1,%2,%3};"
        : "+f"(c[0]), "+f"(c[1]), "+f"(c[2]), "+f"(c[3])
        : "r"(a0), "r"(a1), "r"(a2), "r"(a3), "r"(b0), "r"(b1));
}

// ---------------- 3xTF32 tensor-core GEMM (+ optional gate*tanh epilogue) ----
// (unchanged from R12 — validated)
template <int MODE>
__global__ __launch_bounds__(256)
void proj_mma_kernel(const float* __restrict__ X, const float* __restrict__ W,
                     const float* __restrict__ gate, float* __restrict__ out, int M)
{
    __shared__ float  Xs[128 * 68];
    __shared__ float4 Bfrag[8 * 8 * 32];

    const int t    = threadIdx.x;
    const int row0 = blockIdx.x * 128;

    {
        const int lane = t & 31;
        const int kk   = t >> 5;
        const int grp  = lane >> 2;
        const int tig  = lane & 3;
        const int base = (kk * 8 + tig) * 64 + grp;
        #pragma unroll
        for (int nt = 0; nt < 8; nt++) {
            float v0 = __ldg(&W[base + nt * 8]);
            float v1 = __ldg(&W[base + 4 * 64 + nt * 8]);
            float h0 = __uint_as_float(tf_hi(v0));
            float h1 = __uint_as_float(tf_hi(v1));
            float l0 = __uint_as_float(tf_hi(v0 - h0));
            float l1 = __uint_as_float(tf_hi(v1 - h1));
            Bfrag[(nt * 8 + kk) * 32 + lane] = make_float4(h0, h1, l0, l1);
        }
    }
    {
        const float4* X4 = (const float4*)X;
        #pragma unroll
        for (int jj = 0; jj < 8; jj++) {
            int i4  = t + jj * 256;
            int r   = i4 >> 4;
            int kq  = i4 & 15;
            int row = row0 + r;
            float4 v = make_float4(0.f, 0.f, 0.f, 0.f);
            if (row < M) v = X4[row * 16 + kq];
            float* p = &Xs[r * 68 + kq * 4];
            p[0] = v.x; p[1] = v.y; p[2] = v.z; p[3] = v.w;
        }
    }
    __syncthreads();

    const int lane = t & 31;
    const int w    = t >> 5;
    const int mw   = w >> 1;
    const int nw   = w & 1;
    const int grp  = lane >> 2;
    const int tig  = lane & 3;

    float acc[2][4][4];
    #pragma unroll
    for (int mt = 0; mt < 2; mt++)
        #pragma unroll
        for (int nt = 0; nt < 4; nt++)
            #pragma unroll
            for (int j = 0; j < 4; j++) acc[mt][nt][j] = 0.f;

    const float* xr00 = &Xs[(mw * 32 +      grp) * 68];
    const float* xr01 = &Xs[(mw * 32 +  8 + grp) * 68];
    const float* xr10 = &Xs[(mw * 32 + 16 + grp) * 68];
    const float* xr11 = &Xs[(mw * 32 + 24 + grp) * 68];

    #pragma unroll
    for (int kk = 0; kk < 8; kk++) {
        const int kb = kk * 8;
        unsigned ah[2][4], al[2][4];
        {
            float x0, x1, x2, x3;
            x0 = xr00[kb + tig]; x1 = xr01[kb + tig];
            x2 = xr00[kb + tig + 4]; x3 = xr01[kb + tig + 4];
            ah[0][0] = tf_hi(x0); al[0][0] = tf_hi(x0 - __uint_as_float(ah[0][0]));
            ah[0][1] = tf_hi(x1); al[0][1] = tf_hi(x1 - __uint_as_float(ah[0][1]));
            ah[0][2] = tf_hi(x2); al[0][2] = tf_hi(x2 - __uint_as_float(ah[0][2]));
            ah[0][3] = tf_hi(x3); al[0][3] = tf_hi(x3 - __uint_as_float(ah[0][3]));
            x0 = xr10[kb + tig]; x1 = xr11[kb + tig];
            x2 = xr10[kb + tig + 4]; x3 = xr11[kb + tig + 4];
            ah[1][0] = tf_hi(x0); al[1][0] = tf_hi(x0 - __uint_as_float(ah[1][0]));
            ah[1][1] = tf_hi(x1); al[1][1] = tf_hi(x1 - __uint_as_float(ah[1][1]));
            ah[1][2] = tf_hi(x2); al[1][2] = tf_hi(x2 - __uint_as_float(ah[1][2]));
            ah[1][3] = tf_hi(x3); al[1][3] = tf_hi(x3 - __uint_as_float(ah[1][3]));
        }
        #pragma unroll
        for (int nt = 0; nt < 4; nt++) {
            float4 b = Bfrag[((nw * 4 + nt) * 8 + kk) * 32 + lane];
            unsigned bh0 = __float_as_uint(b.x);
            unsigned bh1 = __float_as_uint(b.y);
            unsigned bl0 = __float_as_uint(b.z);
            unsigned bl1 = __float_as_uint(b.w);
            #pragma unroll
            for (int mt = 0; mt < 2; mt++) {
                mma_tf32(acc[mt][nt], ah[mt][0], ah[mt][1], ah[mt][2], ah[mt][3], bh0, bh1);
                mma_tf32(acc[mt][nt], al[mt][0], al[mt][1], al[mt][2], al[mt][3], bh0, bh1);
                mma_tf32(acc[mt][nt], ah[mt][0], ah[mt][1], ah[mt][2], ah[mt][3], bl0, bl1);
            }
        }
    }

    #pragma unroll
    for (int mt = 0; mt < 2; mt++) {
        const int r0 = row0 + mw * 32 + mt * 16 + grp;
        const int r1 = r0 + 8;
        #pragma unroll
        for (int nt = 0; nt < 4; nt++) {
            const int c = nw * 32 + nt * 8 + tig * 2;
            if (r0 < M) {
                float2 o;
                if (MODE == 1) {
                    float2 g = *(const float2*)&gate[r0 * 64 + c];
                    o.x = tanhf(acc[mt][nt][0] * g.x);
                    o.y = tanhf(acc[mt][nt][1] * g.y);
                } else {
                    o.x = acc[mt][nt][0]; o.y = acc[mt][nt][1];
                }
                *(float2*)&out[r0 * 64 + c] = o;
            }
            if (r1 < M) {
                float2 o;
                if (MODE == 1) {
                    float2 g = *(const float2*)&gate[r1 * 64 + c];
                    o.x = tanhf(acc[mt][nt][2] * g.x);
                    o.y = tanhf(acc[mt][nt][3] * g.y);
                } else {
                    o.x = acc[mt][nt][2]; o.y = acc[mt][nt][3];
                }
                *(float2*)&out[r1 * 64 + c] = o;
            }
        }
    }
}

// ---------------- CSR build ---------------------------------------------------
__global__ __launch_bounds__(256)
void hist_kernel(const int* __restrict__ node_idx, const int* __restrict__ hedge_idx)
{
    int i = blockIdx.x * 256 + threadIdx.x;
    if (i < N_INC) {
        atomicAdd(&g_hist[__ldg(&node_idx[i])], 1);
        atomicAdd(&g_hist[N_NODES + __ldg(&hedge_idx[i])], 1);
    }
}

// 3-pass exclusive scan of g_hist[N_SEG] -> g_off
__global__ __launch_bounds__(1024)
void scan1_kernel()
{
    __shared__ int sh[1024];
    int b = blockIdx.x, t = threadIdx.x;
    int base = b * 4096 + t * 4;
    int v[4]; int s = 0;
    #pragma unroll
    for (int j = 0; j < 4; j++) {
        int x = (base + j < N_SEG) ? g_hist[base + j] : 0;
        v[j] = s; s += x;
    }
    sh[t] = s; __syncthreads();
    for (int ofs = 1; ofs < 1024; ofs <<= 1) {
        int x = 0;
        if (t >= ofs) x = sh[t - ofs];
        __syncthreads();
        if (t >= ofs) sh[t] += x;
        __syncthreads();
    }
    int excl = sh[t] - s;
    if (t == 1023) g_blocksums[b] = sh[t];
    #pragma unroll
    for (int j = 0; j < 4; j++)
        if (base + j < N_SEG) g_off[base + j] = excl + v[j];
}

__global__ __launch_bounds__(128)
void scan2_kernel()
{
    __shared__ int sh[128];
    int t = threadIdx.x;
    int s = (t < SCAN_BLOCKS) ? g_blocksums[t] : 0;
    sh[t] = s; __syncthreads();
    for (int ofs = 1; ofs < 128; ofs <<= 1) {
        int x = 0;
        if (t >= ofs) x = sh[t - ofs];
        __syncthreads();
        if (t >= ofs) sh[t] += x;
        __syncthreads();
    }
    g_blocksums[t] = sh[t] - s;          // exclusive block offsets
    if (t == 0) g_off[N_SEG] = 2 * N_INC;
}

__global__ __launch_bounds__(1024)
void scan3_kernel()
{
    int b = blockIdx.x, t = threadIdx.x;
    int add = g_blocksums[b];
    int base = b * 4096;
    #pragma unroll
    for (int j = 0; j < 4; j++) {
        int i = base + t + j * 1024;
        if (i < N_SEG) g_off[i] += add;
    }
}

// fill adjacency: for node n -> hedge ids; for hedge h -> node ids
__global__ __launch_bounds__(256)
void reorder_kernel(const int* __restrict__ node_idx, const int* __restrict__ hedge_idx)
{
    int i = blockIdx.x * 256 + threadIdx.x;
    if (i < N_INC) {
        int n = __ldg(&node_idx[i]);
        int h = __ldg(&hedge_idx[i]);
        int pn = atomicAdd(&g_hist[n], 1);
        g_ord[g_off[n] + pn] = h;
        int ph = atomicAdd(&g_hist[N_NODES + h], 1);
        g_ord[g_off[N_NODES + h] + ph] = n;
    }
}

// ---------------- CSR segment-sum gather -------------------------------------
// dst[s] = sum over adjacency of src rows (64 f32 each). 16 lanes/segment,
// one float4 per lane, deg-loop unrolled by 2 for MLP.
__global__ __launch_bounds__(256)
void gather_kernel(const float* __restrict__ src, float* __restrict__ dst,
                   int seg_base, int n_seg)
{
    int s = blockIdx.x * 16 + (threadIdx.x >> 4);
    int j = threadIdx.x & 15;
    if (s >= n_seg) return;
    int beg = __ldg(&g_off[seg_base + s]);
    int end = __ldg(&g_off[seg_base + s + 1]);
    const float4* src4 = (const float4*)src;
    float4 acc = make_float4(0.f, 0.f, 0.f, 0.f);
    int i = beg;
    for (; i + 1 < end; i += 2) {
        int r0 = __ldg(&g_ord[i]);
        int r1 = __ldg(&g_ord[i + 1]);
        float4 a = src4[r0 * 16 + j];
        float4 b = src4[r1 * 16 + j];
        acc.x += a.x + b.x;
        acc.y += a.y + b.y;
        acc.z += a.z + b.z;
        acc.w += a.w + b.w;
    }
    if (i < end) {
        int r0 = __ldg(&g_ord[i]);
        float4 a = src4[r0 * 16 + j];
        acc.x += a.x; acc.y += a.y; acc.z += a.z; acc.w += a.w;
    }
    ((float4*)dst)[s * 16 + j] = acc;
}

// ---------------- launch ------------------------------------------------------
extern "C" void kernel_launch(void* const* d_in, const int* in_sizes, int n_in,
                              void* d_out, int out_size)
{
    const float* node_f    = (const float*)d_in[0];
    const float* hedge_f   = (const float*)d_in[1];
    const float* W_nn      = (const float*)d_in[2];
    const float* W_nh      = (const float*)d_in[3];
    const float* W_hh      = (const float*)d_in[4];
    const float* W_hn      = (const float*)d_in[5];
    const int*   node_idx  = (const int*)d_in[6];
    const int*   hedge_idx = (const int*)d_in[7];

    float* out_node  = (float*)d_out;                       // [N_NODES, 64]
    float* out_hedge = out_node + (size_t)N_NODES * D;      // [N_HEDGES, 64]

    float *hp, *np, *gn, *gh;
    int   *hist;
    cudaGetSymbolAddress((void**)&hp,   g_hedge_proj);
    cudaGetSymbolAddress((void**)&np,   g_node_proj);
    cudaGetSymbolAddress((void**)&gn,   g_gate_node);
    cudaGetSymbolAddress((void**)&gh,   g_gate_hedge);
    cudaGetSymbolAddress((void**)&hist, g_hist);

    const int grid_n   = (N_NODES  + 127) / 128;   // 1563
    const int grid_h   = (N_HEDGES + 127) / 128;   // 782
    const int grid_inc = (N_INC + 255) / 256;      // 6250
    const int grid_gn  = (N_NODES  + 15) / 16;     // 12500
    const int grid_gh  = (N_HEDGES + 15) / 16;     // 6250

    // ---- CSR build (indices are inputs; rebuilt every launch, deterministic work)
    cudaMemsetAsync(hist, 0, N_SEG * sizeof(int), 0);
    hist_kernel<<<grid_inc, 256>>>(node_idx, hedge_idx);
    scan1_kernel<<<SCAN_BLOCKS, 1024>>>();
    scan2_kernel<<<1, 128>>>();
    scan3_kernel<<<SCAN_BLOCKS, 1024>>>();
    cudaMemsetAsync(hist, 0, N_SEG * sizeof(int), 0);   // reuse as cursors
    reorder_kernel<<<grid_inc, 256>>>(node_idx, hedge_idx);

    // ---- pipeline
    // 1) hedge_proj = hedge_features @ W_nh
    proj_mma_kernel<0><<<grid_h, 256>>>(hedge_f, W_nh, nullptr, hp, N_HEDGES);
    // 2) gate_node[n] = sum_{h in adj(n)} hedge_proj[h]
    gather_kernel<<<grid_gn, 256>>>(hp, gn, 0, N_NODES);
    // 3) new_node = tanh((node_features @ W_nn) * gate_node)
    proj_mma_kernel<1><<<grid_n, 256>>>(node_f, W_nn, gn, out_node, N_NODES);
    // 4) node_proj = new_node @ W_hn
    proj_mma_kernel<0><<<grid_n, 256>>>(out_node, W_hn, nullptr, np, N_NODES);
    // 5) gate_hedge[h] = sum_{n in adj(h)} node_proj[n]
    gather_kernel<<<grid_gh, 256>>>(np, gh, N_NODES, N_HEDGES);
    // 6) new_hedge = tanh((hedge_features @ W_hh) * gate_hedge)
    proj_mma_kernel<1><<<grid_h, 256>>>(hedge_f, W_hh, gh, out_hedge, N_HEDGES);
}